// round 4
// baseline (speedup 1.0000x reference)
#include <cuda_runtime.h>
#include <cstdint>

#define Bb 2
#define Cc 66
#define Tt 32
#define Nn 512
#define TNc (Tt*Nn)          // 16384
#define BTNc (Bb*TNc)        // 32768
#define Ll 2
#define QKd 64
#define Vdim 124
#define Kn 16

// ---------------- device scratch (no cudaMalloc allowed) ----------------
static __device__ float g_proj[33554432];     // [BTN][1024]  (134 MB)
static __device__ int   g_nid[BTNc * Kn];     // neighbor global point ids
static __device__ float g_wcombT[64 * 1024];  // [c][row] transposed combined weights
static __device__ float g_bias[1024];
static __device__ float g_wpos[2 * 256 * 4];  // [l][row(252 pad 256)][4]

// Row layout (per point, stride 1024):
//   l*512 + 0   .. 251 : center proj (q 0..63 | k 64..127 | v 128..251)  (+bias)
//   l*512 + 256 .. 507 : neighbor proj (same order, no bias)

// ---------------- K0: weight prep ----------------
__global__ __launch_bounds__(256) void prep_kernel(
        const float* __restrict__ Wqk, const float* __restrict__ bqk,
        const float* __restrict__ Wv,  const float* __restrict__ bv) {
    int i = blockIdx.x * blockDim.x + threadIdx.x;   // 0 .. 65535
    {
        int c = i >> 10, r = i & 1023;
        int l = r >> 9, within = r & 511, typ = within >> 8, o = within & 255;
        float w = 0.f;
        if (o < 252 && c < 62) {
            int col = (typ == 0 ? 4 : 66) + c;
            if (o < 128) w = Wqk[(l * 128 + o) * 128 + col];
            else         w = Wv[(l * 124 + (o - 128)) * 128 + col];
        }
        g_wcombT[c * 1024 + r] = w;
    }
    if (i < 1024) {
        int r = i, l = r >> 9, within = r & 511, typ = within >> 8, o = within & 255;
        float bb = 0.f;
        if (typ == 0 && o < 252) bb = (o < 128) ? bqk[l * 128 + o] : bv[l * 124 + (o - 128)];
        g_bias[r] = bb;
    }
    if (i < 2048) {
        int l = i >> 10, rem = i & 1023, o = rem >> 2, j = rem & 3;
        float w = 0.f;
        if (o < 128)      w = Wqk[(l * 128 + o) * 128 + j];
        else if (o < 252) w = Wv[(l * 124 + (o - 128)) * 128 + j];
        g_wpos[i] = w;
    }
}

// ---------------- K1: kNN (top-16 by (dist2, pool_idx)) ----------------
__global__ __launch_bounds__(128) void knn_kernel(const float* __restrict__ x) {
    int blk = blockIdx.x;
    int bt = blk >> 2, quarter = blk & 3;
    int b = bt / Tt, t = bt % Tt;
    int n = quarter * 128 + threadIdx.x;

    __shared__ float cx_[1536], cy_[1536], cz_[1536];
    const float* xb = x + (size_t)b * Cc * TNc;
    for (int idx = threadIdx.x; idx < 1536; idx += 128) {
        int s = idx >> 9, j = idx & 511;
        int tp = t - 1 + s; tp = tp < 0 ? 0 : (tp > Tt - 1 ? Tt - 1 : tp);
        cx_[idx] = xb[0 * TNc + tp * Nn + j];
        cy_[idx] = xb[1 * TNc + tp * Nn + j];
        cz_[idx] = xb[2 * TNc + tp * Nn + j];
    }
    __syncthreads();

    float px = xb[0 * TNc + t * Nn + n];
    float py = xb[1 * TNc + t * Nn + n];
    float pz = xb[2 * TNc + t * Nn + n];

    unsigned long long key[16];
#pragma unroll
    for (int i = 0; i < 16; i++) key[i] = 0x7F800000FFFFFFFFull;
    float thresh = __uint_as_float(0x7F800000u);  // +inf

    for (int j = 0; j < 1536; j++) {
        float dx = px - cx_[j];
        float dy = py - cy_[j];
        float dz = pz - cz_[j];
        float d = __fadd_rn(__fadd_rn(__fmul_rn(dx, dx), __fmul_rn(dy, dy)), __fmul_rn(dz, dz));
        if (d <= thresh) {
            unsigned long long kk = ((unsigned long long)__float_as_uint(d) << 32) | (unsigned)j;
            if (kk < key[15]) {
                key[15] = kk;
#pragma unroll
                for (int m = 15; m > 0; m--) {
                    unsigned long long a = key[m - 1], c2 = key[m];
                    if (c2 < a) { key[m - 1] = c2; key[m] = a; }
                }
                thresh = __uint_as_float((unsigned)(key[15] >> 32));
            }
        }
    }
    int p = bt * Nn + n;
#pragma unroll
    for (int i = 0; i < 16; i++) {
        int pj = (int)(key[i] & 0xFFFFFFFFu);
        int s = pj >> 9, jn = pj & 511;
        int tp = t - 1 + s; tp = tp < 0 ? 0 : (tp > Tt - 1 ? Tt - 1 : tp);
        g_nid[p * Kn + i] = (b * Tt + tp) * Nn + jn;
    }
}

// ---------------- K2: projection GEMM (1008x62) @ (62 x 32768) ----------------
__global__ __launch_bounds__(256) void proj_kernel(const float* __restrict__ x) {
    __shared__ __align__(16) float Xs[62][128];
    int p0 = blockIdx.x * 128;
    int b = p0 / TNc, rem0 = p0 % TNc;
    const float* xb = x + ((size_t)b * Cc + 4) * TNc + rem0;
    for (int idx = threadIdx.x; idx < 62 * 128; idx += 256) {
        int c = idx >> 7, pp = idx & 127;
        Xs[c][pp] = xb[(size_t)c * TNc + pp];
    }
    __syncthreads();

    int tx = threadIdx.x & 31, ty = threadIdx.x >> 5;
    float* outBase = g_proj + (size_t)(p0 + tx * 4) * 1024;

    for (int chunk = 0; chunk < 16; chunk++) {
        int r0 = ty * 128 + chunk * 8;
        float acc[8][4];
#pragma unroll
        for (int rr = 0; rr < 8; rr++) {
            float bb = g_bias[r0 + rr];
#pragma unroll
            for (int pp = 0; pp < 4; pp++) acc[rr][pp] = bb;
        }
#pragma unroll 2
        for (int c = 0; c < 62; c++) {
            const float4 xv = *(const float4*)&Xs[c][tx * 4];
            const float4 wa = *(const float4*)&g_wcombT[c * 1024 + r0];
            const float4 wb = *(const float4*)&g_wcombT[c * 1024 + r0 + 4];
            float wv[8] = {wa.x, wa.y, wa.z, wa.w, wb.x, wb.y, wb.z, wb.w};
            float xvv[4] = {xv.x, xv.y, xv.z, xv.w};
#pragma unroll
            for (int rr = 0; rr < 8; rr++)
#pragma unroll
                for (int pp = 0; pp < 4; pp++)
                    acc[rr][pp] = fmaf(wv[rr], xvv[pp], acc[rr][pp]);
        }
#pragma unroll
        for (int pp = 0; pp < 4; pp++) {
            float* dst = outBase + (size_t)pp * 1024 + r0;
            *(float4*)dst       = make_float4(acc[0][pp], acc[1][pp], acc[2][pp], acc[3][pp]);
            *(float4*)(dst + 4) = make_float4(acc[4][pp], acc[5][pp], acc[6][pp], acc[7][pp]);
        }
    }
}

// ---------------- K3: attention (dim-major smem, 4 pts concurrent) ----------------
// dynamic smem layout (floats):
#define OFF_QKV   0                        // [4][252][17]   dim-major qkv
#define QKV_STR   17
#define OFF_WPOS  17136                    // [2][256][4]
#define OFF_OUTS  (OFF_WPOS + 2048)        // [16][128]
#define OFF_ES    (OFF_OUTS + 2048)        // [4][16][17]
#define OFF_DELTA (OFF_ES + 1088)          // [4][16] float4
#define OFF_AF    (OFF_DELTA + 256)        // [4][16]
#define OFF_NID   (OFF_AF + 64)            // [4][16] int
#define SMEM_FLOATS (OFF_NID + 64)
#define SMEM_BYTES  (SMEM_FLOATS * 4)

__global__ __launch_bounds__(256) void attn_kernel(const float* __restrict__ x,
                                                   float* __restrict__ out) {
    extern __shared__ __align__(16) float sm[];
    float*  qkvS   = sm + OFF_QKV;
    float*  wposS  = sm + OFF_WPOS;
    float*  outS   = sm + OFF_OUTS;    // [pt][128]
    float*  eS     = sm + OFF_ES;      // [pt2][16][17]
    float4* deltaS = (float4*)(sm + OFF_DELTA);  // [pt2*16 + i]
    float*  afS    = sm + OFF_AF;
    int*    nidS   = (int*)(sm + OFF_NID);

    int tid = threadIdx.x;
    int p0 = blockIdx.x * 16;
    int b = p0 / TNc, rem0 = p0 % TNc;

    for (int i = tid; i < 2048; i += 256) wposS[i] = g_wpos[i];
    if (tid < 64) {
        int pt = tid >> 2, cc = tid & 3;
        outS[pt * 128 + cc] = x[((size_t)b * Cc + cc) * TNc + rem0 + pt];
    }
    __syncthreads();

    for (int l = 0; l < Ll; l++) {
        for (int g = 0; g < 4; g++) {
            // ---- neighbor ids + pos deltas for 4 points ----
            if (tid < 64) {
                int pt2 = tid >> 4, i = tid & 15;
                int pt = g * 4 + pt2;
                int p = p0 + pt;
                int gg = g_nid[p * Kn + i];
                nidS[pt2 * 16 + i] = gg;
                int grem = gg - b * TNc;
                float4 d;
                d.x = x[((size_t)b * Cc + 0) * TNc + rem0 + pt] - x[((size_t)b * Cc + 0) * TNc + grem];
                d.y = x[((size_t)b * Cc + 1) * TNc + rem0 + pt] - x[((size_t)b * Cc + 1) * TNc + grem];
                d.z = x[((size_t)b * Cc + 2) * TNc + rem0 + pt] - x[((size_t)b * Cc + 2) * TNc + grem];
                d.w = x[((size_t)b * Cc + 3) * TNc + rem0 + pt] - x[((size_t)b * Cc + 3) * TNc + grem];
                deltaS[pt2 * 16 + i] = d;
            }
            __syncthreads();

            // ---- assemble qkv (dim-major): thread = (c0, pt2) ----
            {
                int c0 = tid & 63, pt2 = tid >> 6;
                int pt = g * 4 + pt2;
                int p = p0 + pt;
                const float* wp = wposS + l * 1024;
#pragma unroll
                for (int it = 0; it < 4; it++) {
                    int c = c0 + (it << 6);
                    if (c < 252) {
                        float4 w4 = *(const float4*)&wp[c * 4];
                        float ctr = g_proj[(size_t)p * 1024 + l * 512 + c];
                        float* dst = qkvS + (pt2 * 252 + c) * QKV_STR;
#pragma unroll
                        for (int i = 0; i < 16; i++) {
                            float4 dd = deltaS[pt2 * 16 + i];
                            float nbv = g_proj[(size_t)nidS[pt2 * 16 + i] * 1024 + l * 512 + 256 + c];
                            dst[i] = nbv + ctr + w4.x * dd.x + w4.y * dd.y + w4.z * dd.z + w4.w * dd.w;
                        }
                    }
                }
            }
            __syncthreads();

            // ---- energy: thread = (pt2, i, j4) computes e[i][4j..4j+3] ----
            {
                int pt2 = tid >> 6, r = tid & 63, i = r >> 2, j4 = (r & 3) << 2;
                const float* qb = qkvS + (pt2 * 252) * QKV_STR;
                float a0 = 0.f, a1 = 0.f, a2 = 0.f, a3 = 0.f;
#pragma unroll 8
                for (int c = 0; c < 64; c++) {
                    float qv = qb[c * QKV_STR + i];
                    const float* kr = qb + (64 + c) * QKV_STR + j4;
                    a0 = fmaf(qv, kr[0], a0);
                    a1 = fmaf(qv, kr[1], a1);
                    a2 = fmaf(qv, kr[2], a2);
                    a3 = fmaf(qv, kr[3], a3);
                }
                float* er = eS + (pt2 * 16 + i) * 17 + j4;
                er[0] = a0 * 0.125f;
                er[1] = a1 * 0.125f;
                er[2] = a2 * 0.125f;
                er[3] = a3 * 0.125f;
            }
            __syncthreads();

            // ---- softmax column 0 ----
            if (tid < 64) {
                int pt2 = tid >> 4, i = tid & 15;
                const float* er = eS + (pt2 * 16 + i) * 17;
                float m = -1e30f;
#pragma unroll
                for (int j = 0; j < 16; j++) m = fmaxf(m, er[j]);
                float sum = 0.f;
#pragma unroll
                for (int j = 0; j < 16; j++) sum += __expf(er[j] - m);
                afS[pt2 * 16 + i] = __expf(er[0] - m) / sum;
            }
            __syncthreads();

            // ---- weighted v sum: 4 pts x 124 channels ----
            for (int idx = tid; idx < 4 * 124; idx += 256) {
                int pt2 = idx / 124, c = idx - pt2 * 124;
                const float* vr = qkvS + (pt2 * 252 + 128 + c) * QKV_STR;
                const float* af = afS + pt2 * 16;
                float s = 0.f;
#pragma unroll
                for (int i = 0; i < 16; i++) s = fmaf(af[i], vr[i], s);
                outS[(g * 4 + pt2) * 128 + 4 + c] = s;
            }
            __syncthreads();
        }
        // ---- coalesced write of this layer's 16 points ----
        for (int idx = tid; idx < 2048; idx += 256) {
            int c = idx >> 4, pt = idx & 15;
            out[((size_t)(l * Bb + b) * 128 + c) * TNc + rem0 + pt] = outS[pt * 128 + c];
        }
        __syncthreads();
    }
}

// ---------------- launch ----------------
extern "C" void kernel_launch(void* const* d_in, const int* in_sizes, int n_in,
                              void* d_out, int out_size) {
    const float* x   = (const float*)d_in[0];
    const float* Wqk = (const float*)d_in[1];
    const float* bqk = (const float*)d_in[2];
    const float* Wv  = (const float*)d_in[3];
    const float* bv  = (const float*)d_in[4];
    float* out = (float*)d_out;

    cudaFuncSetAttribute(attn_kernel, cudaFuncAttributeMaxDynamicSharedMemorySize, SMEM_BYTES);

    prep_kernel<<<256, 256>>>(Wqk, bqk, Wv, bv);
    knn_kernel<<<Bb * Tt * 4, 128>>>(x);
    proj_kernel<<<BTNc / 128, 256>>>(x);
    attn_kernel<<<BTNc / 16, 256, SMEM_BYTES>>>(x, out);
}

// round 5
// speedup vs baseline: 1.3001x; 1.3001x over previous
#include <cuda_runtime.h>
#include <cstdint>

#define Bb 2
#define Cc 66
#define Tt 32
#define Nn 512
#define TNc (Tt*Nn)          // 16384
#define BTNc (Bb*TNc)        // 32768
#define Ll 2
#define QKd 64
#define Vdim 124
#define Kn 16

// ---------------- device scratch (no cudaMalloc allowed) ----------------
static __device__ float g_proj[33554432];     // [BTN][1024]  (134 MB)
static __device__ int   g_nid[BTNc * Kn];     // neighbor global point ids
static __device__ float g_wcombT[64 * 1024];  // [c][row] transposed combined weights
static __device__ float g_bias[1024];
static __device__ float g_wpos[2 * 256 * 4];  // [l][row(252 pad 256)][4]

// ---------------- K0: weight prep ----------------
__global__ __launch_bounds__(256) void prep_kernel(
        const float* __restrict__ Wqk, const float* __restrict__ bqk,
        const float* __restrict__ Wv,  const float* __restrict__ bv) {
    int i = blockIdx.x * blockDim.x + threadIdx.x;   // 0 .. 65535
    {
        int c = i >> 10, r = i & 1023;
        int l = r >> 9, within = r & 511, typ = within >> 8, o = within & 255;
        float w = 0.f;
        if (o < 252 && c < 62) {
            int col = (typ == 0 ? 4 : 66) + c;
            if (o < 128) w = Wqk[(l * 128 + o) * 128 + col];
            else         w = Wv[(l * 124 + (o - 128)) * 128 + col];
        }
        g_wcombT[c * 1024 + r] = w;
    }
    if (i < 1024) {
        int r = i, l = r >> 9, within = r & 511, typ = within >> 8, o = within & 255;
        float bb = 0.f;
        if (typ == 0 && o < 252) bb = (o < 128) ? bqk[l * 128 + o] : bv[l * 124 + (o - 128)];
        g_bias[r] = bb;
    }
    if (i < 2048) {
        int l = i >> 10, rem = i & 1023, o = rem >> 2, j = rem & 3;
        float w = 0.f;
        if (o < 128)      w = Wqk[(l * 128 + o) * 128 + j];
        else if (o < 252) w = Wv[(l * 124 + (o - 128)) * 128 + j];
        g_wpos[i] = w;
    }
}

// ---------------- K1: kNN ----------------
// Rank candidates by e = |c|^2 - 2 p.c  (same order as dist^2 for fixed p).
// u64 key = (ordered_u32(e) << 32) | pool_idx ; sentinel encodes +inf.
__device__ __forceinline__ void insert16(unsigned long long* key, float e,
                                         unsigned j, float& thresh) {
    unsigned bits = __float_as_uint(e);
    unsigned u = bits ^ ((unsigned)((int)bits >> 31) | 0x80000000u);
    unsigned long long kk = ((unsigned long long)u << 32) | j;
    if (kk < key[15]) {
        key[15] = kk;
#pragma unroll
        for (int m = 15; m > 0; m--) {
            unsigned long long a = key[m - 1], c2 = key[m];
            if (c2 < a) { key[m - 1] = c2; key[m] = a; }
        }
        unsigned ut = (unsigned)(key[15] >> 32);
        unsigned bt2 = (ut & 0x80000000u) ? (ut ^ 0x80000000u) : ~ut;
        thresh = __uint_as_float(bt2);
    }
}

__device__ __forceinline__ void merge16(const unsigned long long* a,
                                        const unsigned long long* b,
                                        unsigned long long* o) {
    int ia = 0, ib = 0;
#pragma unroll
    for (int i = 0; i < 16; i++) {
        unsigned long long va = a[ia], vb = b[ib];
        if (va <= vb) { o[i] = va; ia++; } else { o[i] = vb; ib++; }
    }
}

__global__ __launch_bounds__(128) void knn_kernel(const float* __restrict__ x) {
    // block = 32 points of one (b,t); 4 scanners per point
    int blk = blockIdx.x;          // 0..1023
    int bt = blk >> 4, seg = blk & 15;
    int b = bt / Tt, t = bt % Tt;
    int n0 = seg * 32;
    int tid = threadIdx.x;

    __shared__ __align__(16) float4 pool[1536];                  // 24 KB
    __shared__ unsigned long long kbuf[32][4][16];               // 16 KB
    unsigned long long* merged = (unsigned long long*)pool;      // overlay [32][2][16]

    const float* xb = x + (size_t)b * Cc * TNc;
    for (int idx = tid; idx < 1536; idx += 128) {
        int s = idx >> 9, j = idx & 511;
        int tp = t - 1 + s; tp = tp < 0 ? 0 : (tp > Tt - 1 ? Tt - 1 : tp);
        float cx = xb[0 * TNc + tp * Nn + j];
        float cy = xb[1 * TNc + tp * Nn + j];
        float cz = xb[2 * TNc + tp * Nn + j];
        float cc = fmaf(cx, cx, fmaf(cy, cy, cz * cz));
        pool[idx] = make_float4(cx, cy, cz, cc);
    }
    __syncthreads();

    int pt = tid >> 2, h = tid & 3;
    int n = n0 + pt;
    float px = xb[0 * TNc + t * Nn + n];
    float py = xb[1 * TNc + t * Nn + n];
    float pz = xb[2 * TNc + t * Nn + n];

    unsigned long long key[16];
#pragma unroll
    for (int i = 0; i < 16; i++) key[i] = 0xFF800000FFFFFFFFull;  // enc(+inf)|invalid
    float thresh = __uint_as_float(0x7F800000u);                  // +inf

    int j0 = h * 384;
    for (int jj = 0; jj < 384; jj += 4) {
        float4 c0 = pool[j0 + jj + 0];
        float4 c1 = pool[j0 + jj + 1];
        float4 c2 = pool[j0 + jj + 2];
        float4 c3 = pool[j0 + jj + 3];
        float e0 = fmaf(-2.f, fmaf(px, c0.x, fmaf(py, c0.y, pz * c0.z)), c0.w);
        float e1 = fmaf(-2.f, fmaf(px, c1.x, fmaf(py, c1.y, pz * c1.z)), c1.w);
        float e2 = fmaf(-2.f, fmaf(px, c2.x, fmaf(py, c2.y, pz * c2.z)), c2.w);
        float e3 = fmaf(-2.f, fmaf(px, c3.x, fmaf(py, c3.y, pz * c3.z)), c3.w);
        float m = fminf(fminf(e0, e1), fminf(e2, e3));
        if (m <= thresh) {
            if (e0 <= thresh) insert16(key, e0, (unsigned)(j0 + jj + 0), thresh);
            if (e1 <= thresh) insert16(key, e1, (unsigned)(j0 + jj + 1), thresh);
            if (e2 <= thresh) insert16(key, e2, (unsigned)(j0 + jj + 2), thresh);
            if (e3 <= thresh) insert16(key, e3, (unsigned)(j0 + jj + 3), thresh);
        }
    }
#pragma unroll
    for (int i = 0; i < 16; i++) kbuf[pt][h][i] = key[i];
    __syncthreads();

    if (h < 2) merge16(kbuf[pt][2 * h], kbuf[pt][2 * h + 1], &merged[(pt * 2 + h) * 16]);
    __syncthreads();

    if (h == 0) {
        unsigned long long fin[16];
        merge16(&merged[(pt * 2) * 16], &merged[(pt * 2 + 1) * 16], fin);
        int p = bt * Nn + n;
#pragma unroll
        for (int i = 0; i < 16; i++) {
            int pj = (int)(fin[i] & 0xFFFFFFFFu);
            int s = pj >> 9, jn = pj & 511;
            int tp = t - 1 + s; tp = tp < 0 ? 0 : (tp > Tt - 1 ? Tt - 1 : tp);
            g_nid[p * Kn + i] = (b * Tt + tp) * Nn + jn;
        }
    }
}

// ---------------- K2: projection GEMM (1008x62) @ (62 x 32768) ----------------
__global__ __launch_bounds__(256) void proj_kernel(const float* __restrict__ x) {
    __shared__ __align__(16) float Xs[62][128];
    int p0 = blockIdx.x * 128;
    int b = p0 / TNc, rem0 = p0 % TNc;
    const float* xb = x + ((size_t)b * Cc + 4) * TNc + rem0;
    for (int idx = threadIdx.x; idx < 62 * 128; idx += 256) {
        int c = idx >> 7, pp = idx & 127;
        Xs[c][pp] = xb[(size_t)c * TNc + pp];
    }
    __syncthreads();

    int tx = threadIdx.x & 31, ty = threadIdx.x >> 5;
    float* outBase = g_proj + (size_t)(p0 + tx * 4) * 1024;

    for (int chunk = 0; chunk < 16; chunk++) {
        int r0 = ty * 128 + chunk * 8;
        float acc[8][4];
#pragma unroll
        for (int rr = 0; rr < 8; rr++) {
            float bb = g_bias[r0 + rr];
#pragma unroll
            for (int pp = 0; pp < 4; pp++) acc[rr][pp] = bb;
        }
#pragma unroll 2
        for (int c = 0; c < 62; c++) {
            const float4 xv = *(const float4*)&Xs[c][tx * 4];
            const float4 wa = *(const float4*)&g_wcombT[c * 1024 + r0];
            const float4 wb = *(const float4*)&g_wcombT[c * 1024 + r0 + 4];
            float wv[8] = {wa.x, wa.y, wa.z, wa.w, wb.x, wb.y, wb.z, wb.w};
            float xvv[4] = {xv.x, xv.y, xv.z, xv.w};
#pragma unroll
            for (int rr = 0; rr < 8; rr++)
#pragma unroll
                for (int pp = 0; pp < 4; pp++)
                    acc[rr][pp] = fmaf(wv[rr], xvv[pp], acc[rr][pp]);
        }
#pragma unroll
        for (int pp = 0; pp < 4; pp++) {
            float* dst = outBase + (size_t)pp * 1024 + r0;
            *(float4*)dst       = make_float4(acc[0][pp], acc[1][pp], acc[2][pp], acc[3][pp]);
            *(float4*)(dst + 4) = make_float4(acc[4][pp], acc[5][pp], acc[6][pp], acc[7][pp]);
        }
    }
}

// ---------------- K3: attention (dim-major, 2 independent 128-thread groups) ----------------
// dynamic smem floats:
#define QKV_STR   17
#define GQKV      (252 * QKV_STR)             // 4284 per group
#define OFF_QKV   0                           // [2][252][17]
#define OFF_WPOS  (2 * GQKV)                  // 8568 : [2][256][4]
#define OFF_OUTS  (OFF_WPOS + 2048)           // [16][128]
#define OFF_ES    (OFF_OUTS + 2048)           // [2][16*17]
#define OFF_DELTA (OFF_ES + 2 * 272)          // [2][16] float4
#define OFF_AF    (OFF_DELTA + 128)           // [2][16]
#define OFF_NID   (OFF_AF + 32)               // [2][16] int
#define SMEM_FLOATS (OFF_NID + 32)
#define SMEM_BYTES  (SMEM_FLOATS * 4)

__device__ __forceinline__ void bar_group(int gi) {
    asm volatile("bar.sync %0, 128;" :: "r"(gi + 1) : "memory");
}

__global__ __launch_bounds__(256) void attn_kernel(const float* __restrict__ x,
                                                   float* __restrict__ out) {
    extern __shared__ __align__(16) float sm[];
    int tid = threadIdx.x;
    int gi = tid >> 7, gt = tid & 127;

    float*  qkv    = sm + OFF_QKV + gi * GQKV;
    float*  wposS  = sm + OFF_WPOS;
    float*  outS   = sm + OFF_OUTS;
    float*  eS     = sm + OFF_ES + gi * 272;     // [16][17]
    float4* deltaS = (float4*)(sm + OFF_DELTA) + gi * 16;
    float*  afS    = sm + OFF_AF + gi * 16;
    int*    nidS   = (int*)(sm + OFF_NID) + gi * 16;

    int p0 = blockIdx.x * 16;
    int b = p0 / TNc, rem0 = p0 % TNc;

    for (int i = tid; i < 2048; i += 256) wposS[i] = g_wpos[i];
    if (tid < 64) {
        int pt = tid >> 2, cc = tid & 3;
        outS[pt * 128 + cc] = x[((size_t)b * Cc + cc) * TNc + rem0 + pt];
    }
    __syncthreads();

    for (int l = 0; l < Ll; l++) {
        for (int it = 0; it < 8; it++) {
            int pt = gi * 8 + it;
            int p = p0 + pt;

            // ph0: neighbor ids + deltas
            if (gt < 16) {
                int gg = g_nid[p * Kn + gt];
                nidS[gt] = gg;
                int grem = gg - b * TNc;
                float4 d;
                d.x = x[((size_t)b * Cc + 0) * TNc + rem0 + pt] - x[((size_t)b * Cc + 0) * TNc + grem];
                d.y = x[((size_t)b * Cc + 1) * TNc + rem0 + pt] - x[((size_t)b * Cc + 1) * TNc + grem];
                d.z = x[((size_t)b * Cc + 2) * TNc + rem0 + pt] - x[((size_t)b * Cc + 2) * TNc + grem];
                d.w = x[((size_t)b * Cc + 3) * TNc + rem0 + pt] - x[((size_t)b * Cc + 3) * TNc + grem];
                deltaS[gt] = d;
            }
            bar_group(gi);

            // ph1: assemble qkv (dim-major rows of 16 neighbors)
#pragma unroll
            for (int half = 0; half < 2; half++) {
                int c = gt + half * 128;
                if (c < 252) {
                    float4 w4 = *(const float4*)&wposS[l * 1024 + c * 4];
                    float ctr = g_proj[(size_t)p * 1024 + l * 512 + c];
                    float* dst = qkv + c * QKV_STR;
#pragma unroll
                    for (int i = 0; i < 16; i++) {
                        float4 dd = deltaS[i];
                        float nbv = __ldg(&g_proj[(size_t)nidS[i] * 1024 + l * 512 + 256 + c]);
                        dst[i] = nbv + ctr + w4.x * dd.x + w4.y * dd.y + w4.z * dd.z + w4.w * dd.w;
                    }
                }
            }
            bar_group(gi);

            // ph2: energy  thread = (i = gt>>3, jh = gt&7), j in {jh, jh+8}
            {
                int i = gt >> 3, jh = gt & 7;
                const float* qb = qkv;
                const float* kb = qkv + 64 * QKV_STR;
                float a0 = 0.f, a1 = 0.f;
#pragma unroll 16
                for (int c = 0; c < 64; c++) {
                    float qv = qb[c * QKV_STR + i];
                    a0 = fmaf(qv, kb[c * QKV_STR + jh], a0);
                    a1 = fmaf(qv, kb[c * QKV_STR + jh + 8], a1);
                }
                eS[i * 17 + jh] = a0 * 0.125f;
                eS[i * 17 + jh + 8] = a1 * 0.125f;
            }
            bar_group(gi);

            // ph3: softmax column 0
            if (gt < 16) {
                const float* er = eS + gt * 17;
                float m = -1e30f;
#pragma unroll
                for (int j = 0; j < 16; j++) m = fmaxf(m, er[j]);
                float sum = 0.f;
#pragma unroll
                for (int j = 0; j < 16; j++) sum += __expf(er[j] - m);
                afS[gt] = __expf(er[0] - m) / sum;
            }
            bar_group(gi);

            // ph4: weighted v sum
            if (gt < 124) {
                const float* vr = qkv + (128 + gt) * QKV_STR;
                float s = 0.f;
#pragma unroll
                for (int i = 0; i < 16; i++) s = fmaf(afS[i], vr[i], s);
                outS[pt * 128 + 4 + gt] = s;
            }
            bar_group(gi);
        }
        __syncthreads();
        for (int idx = tid; idx < 2048; idx += 256) {
            int c = idx >> 4, pt = idx & 15;
            out[((size_t)(l * Bb + b) * 128 + c) * TNc + rem0 + pt] = outS[pt * 128 + c];
        }
        __syncthreads();
    }
}

// ---------------- launch ----------------
extern "C" void kernel_launch(void* const* d_in, const int* in_sizes, int n_in,
                              void* d_out, int out_size) {
    const float* x   = (const float*)d_in[0];
    const float* Wqk = (const float*)d_in[1];
    const float* bqk = (const float*)d_in[2];
    const float* Wv  = (const float*)d_in[3];
    const float* bv  = (const float*)d_in[4];
    float* out = (float*)d_out;

    cudaFuncSetAttribute(attn_kernel, cudaFuncAttributeMaxDynamicSharedMemorySize, SMEM_BYTES);

    prep_kernel<<<256, 256>>>(Wqk, bqk, Wv, bv);
    knn_kernel<<<1024, 128>>>(x);
    proj_kernel<<<BTNc / 128, 256>>>(x);
    attn_kernel<<<BTNc / 16, 256, SMEM_BYTES>>>(x, out);
}

// round 6
// speedup vs baseline: 1.4836x; 1.1412x over previous
#include <cuda_runtime.h>
#include <cstdint>

#define Bb 2
#define Cc 66
#define Tt 32
#define Nn 512
#define TNc (Tt*Nn)          // 16384
#define BTNc (Bb*TNc)        // 32768
#define Ll 2
#define Kn 16

// ---------------- device scratch (no cudaMalloc allowed) ----------------
static __device__ float g_proj[33554432];     // [BTN][1024]  (134 MB)
static __device__ int   g_nid[BTNc * Kn];     // neighbor global point ids
static __device__ float g_wcombT[64 * 1024];  // [c][row] transposed combined weights
static __device__ float g_bias[1024];
static __device__ float g_wpos[2 * 256 * 4];  // [l][row(252 pad 256)][4]

// Per-point row layout (stride 1024):
//   l*512 + 0   ..127 : center q|k (+bias)     l*512+128..251 : center v (+bias)
//   l*512 + 256 ..383 : neighbor q|k           l*512+384..507 : neighbor v

// ---------------- K0: weight prep ----------------
__global__ __launch_bounds__(256) void prep_kernel(
        const float* __restrict__ Wqk, const float* __restrict__ bqk,
        const float* __restrict__ Wv,  const float* __restrict__ bv) {
    int i = blockIdx.x * blockDim.x + threadIdx.x;   // 0 .. 65535
    {
        int c = i >> 10, r = i & 1023;
        int l = r >> 9, within = r & 511, typ = within >> 8, o = within & 255;
        float w = 0.f;
        if (o < 252 && c < 62) {
            int col = (typ == 0 ? 4 : 66) + c;
            if (o < 128) w = Wqk[(l * 128 + o) * 128 + col];
            else         w = Wv[(l * 124 + (o - 128)) * 128 + col];
        }
        g_wcombT[c * 1024 + r] = w;
    }
    if (i < 1024) {
        int r = i, l = r >> 9, within = r & 511, typ = within >> 8, o = within & 255;
        float bb = 0.f;
        if (typ == 0 && o < 252) bb = (o < 128) ? bqk[l * 128 + o] : bv[l * 124 + (o - 128)];
        g_bias[r] = bb;
    }
    if (i < 2048) {
        int l = i >> 10, rem = i & 1023, o = rem >> 2, j = rem & 3;
        float w = 0.f;
        if (o < 128)      w = Wqk[(l * 128 + o) * 128 + j];
        else if (o < 252) w = Wv[(l * 124 + (o - 128)) * 128 + j];
        g_wpos[i] = w;
    }
}

// ---------------- K1: kNN ----------------
__device__ __forceinline__ void insert16(unsigned long long* key, float e,
                                         unsigned j, float& thresh) {
    unsigned bits = __float_as_uint(e);
    unsigned u = bits ^ ((unsigned)((int)bits >> 31) | 0x80000000u);
    unsigned long long kk = ((unsigned long long)u << 32) | j;
    if (kk < key[15]) {
        key[15] = kk;
#pragma unroll
        for (int m = 15; m > 0; m--) {
            unsigned long long a = key[m - 1], c2 = key[m];
            if (c2 < a) { key[m - 1] = c2; key[m] = a; }
        }
        unsigned ut = (unsigned)(key[15] >> 32);
        unsigned bt2 = (ut & 0x80000000u) ? (ut ^ 0x80000000u) : ~ut;
        thresh = __uint_as_float(bt2);
    }
}

__device__ __forceinline__ void merge16(const unsigned long long* a,
                                        const unsigned long long* b,
                                        unsigned long long* o) {
    int ia = 0, ib = 0;
#pragma unroll
    for (int i = 0; i < 16; i++) {
        unsigned long long va = a[ia], vb = b[ib];
        if (va <= vb) { o[i] = va; ia++; } else { o[i] = vb; ib++; }
    }
}

__global__ __launch_bounds__(128) void knn_kernel(const float* __restrict__ x) {
    int blk = blockIdx.x;          // 0..1023
    int bt = blk >> 4, seg = blk & 15;
    int b = bt / Tt, t = bt % Tt;
    int n0 = seg * 32;
    int tid = threadIdx.x;

    __shared__ __align__(16) float4 pool[1536];                  // 24 KB
    __shared__ unsigned long long kbuf[32][4][16];               // 16 KB
    unsigned long long* merged = (unsigned long long*)pool;      // overlay [32][2][16]

    const float* xb = x + (size_t)b * Cc * TNc;
    for (int idx = tid; idx < 1536; idx += 128) {
        int s = idx >> 9, j = idx & 511;
        int tp = t - 1 + s; tp = tp < 0 ? 0 : (tp > Tt - 1 ? Tt - 1 : tp);
        float cx = xb[0 * TNc + tp * Nn + j];
        float cy = xb[1 * TNc + tp * Nn + j];
        float cz = xb[2 * TNc + tp * Nn + j];
        float cc = fmaf(cx, cx, fmaf(cy, cy, cz * cz));
        pool[idx] = make_float4(cx, cy, cz, cc);
    }
    __syncthreads();

    int pt = tid >> 2, h = tid & 3;
    int n = n0 + pt;
    float px = xb[0 * TNc + t * Nn + n];
    float py = xb[1 * TNc + t * Nn + n];
    float pz = xb[2 * TNc + t * Nn + n];

    unsigned long long key[16];
#pragma unroll
    for (int i = 0; i < 16; i++) key[i] = 0xFF800000FFFFFFFFull;
    float thresh = __uint_as_float(0x7F800000u);

    int j0 = h * 384;
    for (int jj = 0; jj < 384; jj += 4) {
        float4 c0 = pool[j0 + jj + 0];
        float4 c1 = pool[j0 + jj + 1];
        float4 c2 = pool[j0 + jj + 2];
        float4 c3 = pool[j0 + jj + 3];
        float e0 = fmaf(-2.f, fmaf(px, c0.x, fmaf(py, c0.y, pz * c0.z)), c0.w);
        float e1 = fmaf(-2.f, fmaf(px, c1.x, fmaf(py, c1.y, pz * c1.z)), c1.w);
        float e2 = fmaf(-2.f, fmaf(px, c2.x, fmaf(py, c2.y, pz * c2.z)), c2.w);
        float e3 = fmaf(-2.f, fmaf(px, c3.x, fmaf(py, c3.y, pz * c3.z)), c3.w);
        float m = fminf(fminf(e0, e1), fminf(e2, e3));
        if (m <= thresh) {
            if (e0 <= thresh) insert16(key, e0, (unsigned)(j0 + jj + 0), thresh);
            if (e1 <= thresh) insert16(key, e1, (unsigned)(j0 + jj + 1), thresh);
            if (e2 <= thresh) insert16(key, e2, (unsigned)(j0 + jj + 2), thresh);
            if (e3 <= thresh) insert16(key, e3, (unsigned)(j0 + jj + 3), thresh);
        }
    }
#pragma unroll
    for (int i = 0; i < 16; i++) kbuf[pt][h][i] = key[i];
    __syncthreads();

    if (h < 2) merge16(kbuf[pt][2 * h], kbuf[pt][2 * h + 1], &merged[(pt * 2 + h) * 16]);
    __syncthreads();

    if (h == 0) {
        unsigned long long fin[16];
        merge16(&merged[(pt * 2) * 16], &merged[(pt * 2 + 1) * 16], fin);
        int p = bt * Nn + n;
#pragma unroll
        for (int i = 0; i < 16; i++) {
            int pj = (int)(fin[i] & 0xFFFFFFFFu);
            int s = pj >> 9, jn = pj & 511;
            int tp = t - 1 + s; tp = tp < 0 ? 0 : (tp > Tt - 1 ? Tt - 1 : tp);
            g_nid[p * Kn + i] = (b * Tt + tp) * Nn + jn;
        }
    }
}

// ---------------- K2: projection GEMM (1008x62) @ (62 x 32768) ----------------
__global__ __launch_bounds__(256) void proj_kernel(const float* __restrict__ x) {
    __shared__ __align__(16) float Xs[62][128];
    int p0 = blockIdx.x * 128;
    int b = p0 / TNc, rem0 = p0 % TNc;
    const float* xb = x + ((size_t)b * Cc + 4) * TNc + rem0;
    for (int idx = threadIdx.x; idx < 62 * 128; idx += 256) {
        int c = idx >> 7, pp = idx & 127;
        Xs[c][pp] = xb[(size_t)c * TNc + pp];
    }
    __syncthreads();

    int tx = threadIdx.x & 31, ty = threadIdx.x >> 5;
    float* outBase = g_proj + (size_t)(p0 + tx * 4) * 1024;

    for (int chunk = 0; chunk < 16; chunk++) {
        int r0 = ty * 128 + chunk * 8;
        float acc[8][4];
#pragma unroll
        for (int rr = 0; rr < 8; rr++) {
            float bb = g_bias[r0 + rr];
#pragma unroll
            for (int pp = 0; pp < 4; pp++) acc[rr][pp] = bb;
        }
#pragma unroll 2
        for (int c = 0; c < 62; c++) {
            const float4 xv = *(const float4*)&Xs[c][tx * 4];
            const float4 wa = *(const float4*)&g_wcombT[c * 1024 + r0];
            const float4 wb = *(const float4*)&g_wcombT[c * 1024 + r0 + 4];
            float wv[8] = {wa.x, wa.y, wa.z, wa.w, wb.x, wb.y, wb.z, wb.w};
            float xvv[4] = {xv.x, xv.y, xv.z, xv.w};
#pragma unroll
            for (int rr = 0; rr < 8; rr++)
#pragma unroll
                for (int pp = 0; pp < 4; pp++)
                    acc[rr][pp] = fmaf(wv[rr], xvv[pp], acc[rr][pp]);
        }
#pragma unroll
        for (int pp = 0; pp < 4; pp++) {
            float* dst = outBase + (size_t)pp * 1024 + r0;
            *(float4*)dst       = make_float4(acc[0][pp], acc[1][pp], acc[2][pp], acc[3][pp]);
            *(float4*)(dst + 4) = make_float4(acc[4][pp], acc[5][pp], acc[6][pp], acc[7][pp]);
        }
    }
}

// ---------------- K3: attention v4 ----------------
// Per 128-thread group block (floats): qk[16][132]=2112 | eS[16][17]=272 |
// delta[16]f4=64 | af=16 | nid=16 -> 2480, padded 2496.
#define GSTR 2496
#define SM_FLOATS (2 * GSTR + 2048 + 2048)

__device__ __forceinline__ void bar_group(int gi) {
    asm volatile("bar.sync %0, 128;" :: "r"(gi + 1) : "memory");
}

__global__ __launch_bounds__(256) void attn_kernel(const float* __restrict__ x,
                                                   float* __restrict__ out) {
    __shared__ __align__(16) float sm[SM_FLOATS];
    int tid = threadIdx.x;
    int gi = tid >> 7, gt = tid & 127;

    float*  qk     = sm + gi * GSTR;                 // [16][132]
    float*  eS     = sm + gi * GSTR + 2112;          // [16][17]
    float4* deltaS = (float4*)(sm + gi * GSTR + 2384);
    float*  afS    = sm + gi * GSTR + 2448;
    int*    nidS   = (int*)(sm + gi * GSTR + 2464);
    float*  wposS  = sm + 2 * GSTR;
    float*  outS   = sm + 2 * GSTR + 2048;           // [16][128]

    int p0 = blockIdx.x * 16;
    int b = p0 / TNc, rem0 = p0 % TNc;

    for (int i = tid; i < 2048; i += 256) wposS[i] = g_wpos[i];
    if (tid < 64) {
        int pt = tid >> 2, cc = tid & 3;
        outS[pt * 128 + cc] = x[((size_t)b * Cc + cc) * TNc + rem0 + pt];
    }
    __syncthreads();

    for (int l = 0; l < Ll; l++) {
        for (int it = 0; it < 8; it++) {
            int pt = gi * 8 + it;
            int p = p0 + pt;
            const float* rowC = g_proj + (size_t)p * 1024 + l * 512;

            // ph0: neighbor ids + deltas
            if (gt < 16) {
                int gg = g_nid[p * Kn + gt];
                nidS[gt] = gg;
                int grem = gg - b * TNc;
                float4 d;
                d.x = x[((size_t)b * Cc + 0) * TNc + rem0 + pt] - x[((size_t)b * Cc + 0) * TNc + grem];
                d.y = x[((size_t)b * Cc + 1) * TNc + rem0 + pt] - x[((size_t)b * Cc + 1) * TNc + grem];
                d.z = x[((size_t)b * Cc + 2) * TNc + rem0 + pt] - x[((size_t)b * Cc + 2) * TNc + grem];
                d.w = x[((size_t)b * Cc + 3) * TNc + rem0 + pt] - x[((size_t)b * Cc + 3) * TNc + grem];
                deltaS[gt] = d;
            }
            bar_group(gi);

            // ph1: assemble q,k (i-major). thread = channel c = gt (0..127)
            {
                float4 w4 = *(const float4*)&wposS[l * 1024 + gt * 4];
                float ctr = rowC[gt];
                float base = ctr;
#pragma unroll
                for (int i = 0; i < 16; i++) {
                    float4 dd = deltaS[i];
                    float nbv = __ldg(&g_proj[(size_t)nidS[i] * 1024 + l * 512 + 256 + gt]);
                    qk[i * 132 + gt] = nbv + base + w4.x * dd.x + w4.y * dd.y
                                       + w4.z * dd.z + w4.w * dd.w;
                }
            }
            bar_group(gi);

            // ph2: energy, float4 dots. thread = (i = gt>>3, j = gt&7 and +8)
            {
                int i = gt >> 3, jh = gt & 7;
                const float* qb = qk + i * 132;
                const float* k0 = qk + jh * 132 + 64;
                const float* k1 = qk + (jh + 8) * 132 + 64;
                float a0 = 0.f, a1 = 0.f;
#pragma unroll
                for (int c4 = 0; c4 < 16; c4++) {
                    float4 q4 = *(const float4*)(qb + c4 * 4);
                    float4 ka = *(const float4*)(k0 + c4 * 4);
                    float4 kb = *(const float4*)(k1 + c4 * 4);
                    a0 = fmaf(q4.x, ka.x, a0); a0 = fmaf(q4.y, ka.y, a0);
                    a0 = fmaf(q4.z, ka.z, a0); a0 = fmaf(q4.w, ka.w, a0);
                    a1 = fmaf(q4.x, kb.x, a1); a1 = fmaf(q4.y, kb.y, a1);
                    a1 = fmaf(q4.z, kb.z, a1); a1 = fmaf(q4.w, kb.w, a1);
                }
                eS[i * 17 + jh] = a0 * 0.125f;
                eS[i * 17 + jh + 8] = a1 * 0.125f;
            }
            bar_group(gi);

            // ph3: softmax column 0
            if (gt < 16) {
                const float* er = eS + gt * 17;
                float m = -1e30f;
#pragma unroll
                for (int j = 0; j < 16; j++) m = fmaxf(m, er[j]);
                float sum = 0.f;
#pragma unroll
                for (int j = 0; j < 16; j++) sum += __expf(er[j] - m);
                afS[gt] = __expf(er[0] - m) / sum;
            }
            bar_group(gi);

            // ph4: out_c = S*ctrv + wv.D + sum_i af_i * nbv_ic
            {
                int lane = gt & 31;
                float a = 0.f; float4 dd = make_float4(0.f, 0.f, 0.f, 0.f);
                if (lane < 16) { a = afS[lane]; dd = deltaS[lane]; }
                float s0 = a, dx = a * dd.x, dy = a * dd.y, dz = a * dd.z, dw = a * dd.w;
#pragma unroll
                for (int off = 16; off > 0; off >>= 1) {
                    s0 += __shfl_xor_sync(0xFFFFFFFFu, s0, off);
                    dx += __shfl_xor_sync(0xFFFFFFFFu, dx, off);
                    dy += __shfl_xor_sync(0xFFFFFFFFu, dy, off);
                    dz += __shfl_xor_sync(0xFFFFFFFFu, dz, off);
                    dw += __shfl_xor_sync(0xFFFFFFFFu, dw, off);
                }
                if (gt < 124) {
                    float4 wv = *(const float4*)&wposS[l * 1024 + (128 + gt) * 4];
                    float acc = s0 * rowC[128 + gt]
                              + wv.x * dx + wv.y * dy + wv.z * dz + wv.w * dw;
#pragma unroll
                    for (int i = 0; i < 16; i++)
                        acc = fmaf(afS[i],
                                   __ldg(&g_proj[(size_t)nidS[i] * 1024 + l * 512 + 384 + gt]),
                                   acc);
                    outS[pt * 128 + 4 + gt] = acc;
                }
            }
            bar_group(gi);
        }
        __syncthreads();
        for (int idx = tid; idx < 2048; idx += 256) {
            int c = idx >> 4, pt = idx & 15;
            out[((size_t)(l * Bb + b) * 128 + c) * TNc + rem0 + pt] = outS[pt * 128 + c];
        }
        __syncthreads();
    }
}

// ---------------- launch ----------------
extern "C" void kernel_launch(void* const* d_in, const int* in_sizes, int n_in,
                              void* d_out, int out_size) {
    const float* x   = (const float*)d_in[0];
    const float* Wqk = (const float*)d_in[1];
    const float* bqk = (const float*)d_in[2];
    const float* Wv  = (const float*)d_in[3];
    const float* bv  = (const float*)d_in[4];
    float* out = (float*)d_out;

    prep_kernel<<<256, 256>>>(Wqk, bqk, Wv, bv);
    knn_kernel<<<1024, 128>>>(x);
    proj_kernel<<<BTNc / 128, 256>>>(x);
    attn_kernel<<<BTNc / 16, 256>>>(x, out);
}

// round 7
// speedup vs baseline: 1.8837x; 1.2697x over previous
#include <cuda_runtime.h>
#include <cstdint>

#define Bb 2
#define Cc 66
#define Tt 32
#define Nn 512
#define TNc (Tt*Nn)          // 16384
#define BTNc (Bb*TNc)        // 32768
#define Ll 2
#define Kn 16

// ---------------- device scratch (no cudaMalloc allowed) ----------------
static __device__ float g_proj[33554432];     // [BTN][1024]  (134 MB)
static __device__ int   g_nid[BTNc * Kn];     // neighbor global point ids
static __device__ float g_wcombT[64 * 1024];  // [c][row] transposed combined weights
static __device__ float g_bias[1024];
static __device__ float g_wpos[2 * 256 * 4];  // [l][row(252 pad 256)][4]

// Per-point row layout (stride 1024):
//   l*512 + 0   ..127 : center q|k (+bias)     l*512+128..251 : center v (+bias)
//   l*512 + 256 ..383 : neighbor q|k           l*512+384..507 : neighbor v

// ---------------- K0: weight prep ----------------
__global__ __launch_bounds__(256) void prep_kernel(
        const float* __restrict__ Wqk, const float* __restrict__ bqk,
        const float* __restrict__ Wv,  const float* __restrict__ bv) {
    int i = blockIdx.x * blockDim.x + threadIdx.x;   // 0 .. 65535
    {
        int c = i >> 10, r = i & 1023;
        int l = r >> 9, within = r & 511, typ = within >> 8, o = within & 255;
        float w = 0.f;
        if (o < 252 && c < 62) {
            int col = (typ == 0 ? 4 : 66) + c;
            if (o < 128) w = Wqk[(l * 128 + o) * 128 + col];
            else         w = Wv[(l * 124 + (o - 128)) * 128 + col];
        }
        g_wcombT[c * 1024 + r] = w;
    }
    if (i < 1024) {
        int r = i, l = r >> 9, within = r & 511, typ = within >> 8, o = within & 255;
        float bb = 0.f;
        if (typ == 0 && o < 252) bb = (o < 128) ? bqk[l * 128 + o] : bv[l * 124 + (o - 128)];
        g_bias[r] = bb;
    }
    if (i < 2048) {
        int l = i >> 10, rem = i & 1023, o = rem >> 2, j = rem & 3;
        float w = 0.f;
        if (o < 128)      w = Wqk[(l * 128 + o) * 128 + j];
        else if (o < 252) w = Wv[(l * 124 + (o - 128)) * 128 + j];
        g_wpos[i] = w;
    }
}

// ---------------- K1: kNN v3 (warp-per-point, lane-distributed sorted top-16) ----------------
__global__ __launch_bounds__(256) void knn_kernel(const float* __restrict__ x) {
    // block = 8 warps = 8 points of one (b,t); grid = 64 bt * 64 segs
    int blk = blockIdx.x;            // 0..4095
    int bt = blk >> 6, seg = blk & 63;
    int b = bt / Tt, t = bt % Tt;
    int tid = threadIdx.x, wid = tid >> 5, lane = tid & 31;
    int n = seg * 8 + wid;

    __shared__ __align__(16) float4 pool[1536];   // 24 KB
    const float* xb = x + (size_t)b * Cc * TNc;
    for (int idx = tid; idx < 1536; idx += 256) {
        int s = idx >> 9, j = idx & 511;
        int tp = t - 1 + s; tp = tp < 0 ? 0 : (tp > Tt - 1 ? Tt - 1 : tp);
        float cx = xb[0 * TNc + tp * Nn + j];
        float cy = xb[1 * TNc + tp * Nn + j];
        float cz = xb[2 * TNc + tp * Nn + j];
        float cc = fmaf(cx, cx, fmaf(cy, cy, cz * cz));
        pool[idx] = make_float4(cx, cy, cz, cc);
    }
    __syncthreads();

    float px = xb[0 * TNc + t * Nn + n];
    float py = xb[1 * TNc + t * Nn + n];
    float pz = xb[2 * TNc + t * Nn + n];

    // lanes 0..15 hold the sorted top-16 (ascending u64). Sentinel = max u64,
    // strictly greater than any real key.
    unsigned long long S = ~0ull;
    unsigned long long thresh = ~0ull;   // current 16th best (S of lane 15)

    for (int c0 = 0; c0 < 1536; c0 += 32) {
        int j = c0 + lane;
        float4 cd = pool[j];
        // rank by e = |c|^2 - 2 p.c (same order as dist^2 for fixed p)
        float e = fmaf(-2.f, fmaf(px, cd.x, fmaf(py, cd.y, pz * cd.z)), cd.w);
        unsigned bits = __float_as_uint(e);
        unsigned u = bits ^ ((unsigned)((int)bits >> 31) | 0x80000000u);
        unsigned long long kk = ((unsigned long long)u << 32) | (unsigned)j;

        unsigned mask = __ballot_sync(0xFFFFFFFFu, kk < thresh);
        while (mask) {
            int src = __ffs(mask) - 1;          // ascending j => exact tie order
            mask &= mask - 1;
            unsigned long long val = __shfl_sync(0xFFFFFFFFu, kk, src);
            if (val < thresh) {                  // uniform re-check (stale-safe anyway)
                unsigned long long up = __shfl_up_sync(0xFFFFFFFFu, S, 1);
                if (lane < 16 && val < S)
                    S = (lane > 0 && val < up) ? up : val;
                thresh = __shfl_sync(0xFFFFFFFFu, S, 15);
            }
        }
    }

    if (lane < 16) {
        unsigned pj = (unsigned)(S & 0xFFFFFFFFu);
        int s = (int)(pj >> 9), jn = (int)(pj & 511u);
        int tp = t - 1 + s; tp = tp < 0 ? 0 : (tp > Tt - 1 ? Tt - 1 : tp);
        g_nid[(bt * Nn + n) * Kn + lane] = (b * Tt + tp) * Nn + jn;
    }
}

// ---------------- K2: projection GEMM (1008x62) @ (62 x 32768) ----------------
__global__ __launch_bounds__(256) void proj_kernel(const float* __restrict__ x) {
    __shared__ __align__(16) float Xs[62][128];
    int p0 = blockIdx.x * 128;
    int b = p0 / TNc, rem0 = p0 % TNc;
    const float* xb = x + ((size_t)b * Cc + 4) * TNc + rem0;
    for (int idx = threadIdx.x; idx < 62 * 128; idx += 256) {
        int c = idx >> 7, pp = idx & 127;
        Xs[c][pp] = xb[(size_t)c * TNc + pp];
    }
    __syncthreads();

    int tx = threadIdx.x & 31, ty = threadIdx.x >> 5;
    float* outBase = g_proj + (size_t)(p0 + tx * 4) * 1024;

    for (int chunk = 0; chunk < 16; chunk++) {
        int r0 = ty * 128 + chunk * 8;
        float acc[8][4];
#pragma unroll
        for (int rr = 0; rr < 8; rr++) {
            float bb = g_bias[r0 + rr];
#pragma unroll
            for (int pp = 0; pp < 4; pp++) acc[rr][pp] = bb;
        }
#pragma unroll 2
        for (int c = 0; c < 62; c++) {
            const float4 xv = *(const float4*)&Xs[c][tx * 4];
            const float4 wa = *(const float4*)&g_wcombT[c * 1024 + r0];
            const float4 wb = *(const float4*)&g_wcombT[c * 1024 + r0 + 4];
            float wv[8] = {wa.x, wa.y, wa.z, wa.w, wb.x, wb.y, wb.z, wb.w};
            float xvv[4] = {xv.x, xv.y, xv.z, xv.w};
#pragma unroll
            for (int rr = 0; rr < 8; rr++)
#pragma unroll
                for (int pp = 0; pp < 4; pp++)
                    acc[rr][pp] = fmaf(wv[rr], xvv[pp], acc[rr][pp]);
        }
#pragma unroll
        for (int pp = 0; pp < 4; pp++) {
            float* dst = outBase + (size_t)pp * 1024 + r0;
            *(float4*)dst       = make_float4(acc[0][pp], acc[1][pp], acc[2][pp], acc[3][pp]);
            *(float4*)(dst + 4) = make_float4(acc[4][pp], acc[5][pp], acc[6][pp], acc[7][pp]);
        }
    }
}

// ---------------- K3: attention v4 (unchanged from round 6) ----------------
#define GSTR 2496
#define SM_FLOATS (2 * GSTR + 2048 + 2048)

__device__ __forceinline__ void bar_group(int gi) {
    asm volatile("bar.sync %0, 128;" :: "r"(gi + 1) : "memory");
}

__global__ __launch_bounds__(256) void attn_kernel(const float* __restrict__ x,
                                                   float* __restrict__ out) {
    __shared__ __align__(16) float sm[SM_FLOATS];
    int tid = threadIdx.x;
    int gi = tid >> 7, gt = tid & 127;

    float*  qk     = sm + gi * GSTR;                 // [16][132]
    float*  eS     = sm + gi * GSTR + 2112;          // [16][17]
    float4* deltaS = (float4*)(sm + gi * GSTR + 2384);
    float*  afS    = sm + gi * GSTR + 2448;
    int*    nidS   = (int*)(sm + gi * GSTR + 2464);
    float*  wposS  = sm + 2 * GSTR;
    float*  outS   = sm + 2 * GSTR + 2048;           // [16][128]

    int p0 = blockIdx.x * 16;
    int b = p0 / TNc, rem0 = p0 % TNc;

    for (int i = tid; i < 2048; i += 256) wposS[i] = g_wpos[i];
    if (tid < 64) {
        int pt = tid >> 2, cc = tid & 3;
        outS[pt * 128 + cc] = x[((size_t)b * Cc + cc) * TNc + rem0 + pt];
    }
    __syncthreads();

    for (int l = 0; l < Ll; l++) {
        for (int it = 0; it < 8; it++) {
            int pt = gi * 8 + it;
            int p = p0 + pt;
            const float* rowC = g_proj + (size_t)p * 1024 + l * 512;

            // ph0: neighbor ids + deltas
            if (gt < 16) {
                int gg = g_nid[p * Kn + gt];
                nidS[gt] = gg;
                int grem = gg - b * TNc;
                float4 d;
                d.x = x[((size_t)b * Cc + 0) * TNc + rem0 + pt] - x[((size_t)b * Cc + 0) * TNc + grem];
                d.y = x[((size_t)b * Cc + 1) * TNc + rem0 + pt] - x[((size_t)b * Cc + 1) * TNc + grem];
                d.z = x[((size_t)b * Cc + 2) * TNc + rem0 + pt] - x[((size_t)b * Cc + 2) * TNc + grem];
                d.w = x[((size_t)b * Cc + 3) * TNc + rem0 + pt] - x[((size_t)b * Cc + 3) * TNc + grem];
                deltaS[gt] = d;
            }
            bar_group(gi);

            // ph1: assemble q,k (i-major). thread = channel c = gt (0..127)
            {
                float4 w4 = *(const float4*)&wposS[l * 1024 + gt * 4];
                float base = rowC[gt];
#pragma unroll
                for (int i = 0; i < 16; i++) {
                    float4 dd = deltaS[i];
                    float nbv = __ldg(&g_proj[(size_t)nidS[i] * 1024 + l * 512 + 256 + gt]);
                    qk[i * 132 + gt] = nbv + base + w4.x * dd.x + w4.y * dd.y
                                       + w4.z * dd.z + w4.w * dd.w;
                }
            }
            bar_group(gi);

            // ph2: energy, float4 dots
            {
                int i = gt >> 3, jh = gt & 7;
                const float* qb = qk + i * 132;
                const float* k0 = qk + jh * 132 + 64;
                const float* k1 = qk + (jh + 8) * 132 + 64;
                float a0 = 0.f, a1 = 0.f;
#pragma unroll
                for (int c4 = 0; c4 < 16; c4++) {
                    float4 q4 = *(const float4*)(qb + c4 * 4);
                    float4 ka = *(const float4*)(k0 + c4 * 4);
                    float4 kb = *(const float4*)(k1 + c4 * 4);
                    a0 = fmaf(q4.x, ka.x, a0); a0 = fmaf(q4.y, ka.y, a0);
                    a0 = fmaf(q4.z, ka.z, a0); a0 = fmaf(q4.w, ka.w, a0);
                    a1 = fmaf(q4.x, kb.x, a1); a1 = fmaf(q4.y, kb.y, a1);
                    a1 = fmaf(q4.z, kb.z, a1); a1 = fmaf(q4.w, kb.w, a1);
                }
                eS[i * 17 + jh] = a0 * 0.125f;
                eS[i * 17 + jh + 8] = a1 * 0.125f;
            }
            bar_group(gi);

            // ph3: softmax column 0
            if (gt < 16) {
                const float* er = eS + gt * 17;
                float m = -1e30f;
#pragma unroll
                for (int j = 0; j < 16; j++) m = fmaxf(m, er[j]);
                float sum = 0.f;
#pragma unroll
                for (int j = 0; j < 16; j++) sum += __expf(er[j] - m);
                afS[gt] = __expf(er[0] - m) / sum;
            }
            bar_group(gi);

            // ph4: out_c = S*ctrv + wv.D + sum_i af_i * nbv_ic
            {
                int lane = gt & 31;
                float a = 0.f; float4 dd = make_float4(0.f, 0.f, 0.f, 0.f);
                if (lane < 16) { a = afS[lane]; dd = deltaS[lane]; }
                float s0 = a, dx = a * dd.x, dy = a * dd.y, dz = a * dd.z, dw = a * dd.w;
#pragma unroll
                for (int off = 16; off > 0; off >>= 1) {
                    s0 += __shfl_xor_sync(0xFFFFFFFFu, s0, off);
                    dx += __shfl_xor_sync(0xFFFFFFFFu, dx, off);
                    dy += __shfl_xor_sync(0xFFFFFFFFu, dy, off);
                    dz += __shfl_xor_sync(0xFFFFFFFFu, dz, off);
                    dw += __shfl_xor_sync(0xFFFFFFFFu, dw, off);
                }
                if (gt < 124) {
                    float4 wv = *(const float4*)&wposS[l * 1024 + (128 + gt) * 4];
                    float acc = s0 * rowC[128 + gt]
                              + wv.x * dx + wv.y * dy + wv.z * dz + wv.w * dw;
#pragma unroll
                    for (int i = 0; i < 16; i++)
                        acc = fmaf(afS[i],
                                   __ldg(&g_proj[(size_t)nidS[i] * 1024 + l * 512 + 384 + gt]),
                                   acc);
                    outS[pt * 128 + 4 + gt] = acc;
                }
            }
            bar_group(gi);
        }
        __syncthreads();
        for (int idx = tid; idx < 2048; idx += 256) {
            int c = idx >> 4, pt = idx & 15;
            out[((size_t)(l * Bb + b) * 128 + c) * TNc + rem0 + pt] = outS[pt * 128 + c];
        }
        __syncthreads();
    }
}

// ---------------- launch ----------------
extern "C" void kernel_launch(void* const* d_in, const int* in_sizes, int n_in,
                              void* d_out, int out_size) {
    const float* x   = (const float*)d_in[0];
    const float* Wqk = (const float*)d_in[1];
    const float* bqk = (const float*)d_in[2];
    const float* Wv  = (const float*)d_in[3];
    const float* bv  = (const float*)d_in[4];
    float* out = (float*)d_out;

    prep_kernel<<<256, 256>>>(Wqk, bqk, Wv, bv);
    knn_kernel<<<4096, 256>>>(x);
    proj_kernel<<<BTNc / 128, 256>>>(x);
    attn_kernel<<<BTNc / 16, 256>>>(x, out);
}

// round 8
// speedup vs baseline: 1.9458x; 1.0330x over previous
#include <cuda_runtime.h>
#include <cstdint>

#define Bb 2
#define Cc 66
#define Tt 32
#define Nn 512
#define TNc (Tt*Nn)          // 16384
#define BTNc (Bb*TNc)        // 32768
#define Ll 2
#define Kn 16

// ---------------- device scratch (no cudaMalloc allowed) ----------------
static __device__ float g_proj[33554432];     // [BTN][1024]  (134 MB)
static __device__ int   g_nid[BTNc * Kn];     // neighbor global point ids
static __device__ float g_wcombT[64 * 1024];  // [c][row] transposed combined weights
static __device__ float g_bias[1024];
static __device__ float g_wpos[2 * 256 * 4];  // [l][row(252 pad 256)][4]

// Per-point row layout (stride 1024):
//   l*512 + 0   ..127 : center q|k (+bias)     l*512+128..251 : center v (+bias)
//   l*512 + 256 ..383 : neighbor q|k           l*512+384..507 : neighbor v

// ---------------- K0: weight prep ----------------
__global__ __launch_bounds__(256) void prep_kernel(
        const float* __restrict__ Wqk, const float* __restrict__ bqk,
        const float* __restrict__ Wv,  const float* __restrict__ bv) {
    int i = blockIdx.x * blockDim.x + threadIdx.x;   // 0 .. 65535
    {
        int c = i >> 10, r = i & 1023;
        int l = r >> 9, within = r & 511, typ = within >> 8, o = within & 255;
        float w = 0.f;
        if (o < 252 && c < 62) {
            int col = (typ == 0 ? 4 : 66) + c;
            if (o < 128) w = Wqk[(l * 128 + o) * 128 + col];
            else         w = Wv[(l * 124 + (o - 128)) * 128 + col];
        }
        g_wcombT[c * 1024 + r] = w;
    }
    if (i < 1024) {
        int r = i, l = r >> 9, within = r & 511, typ = within >> 8, o = within & 255;
        float bb = 0.f;
        if (typ == 0 && o < 252) bb = (o < 128) ? bqk[l * 128 + o] : bv[l * 124 + (o - 128)];
        g_bias[r] = bb;
    }
    if (i < 2048) {
        int l = i >> 10, rem = i & 1023, o = rem >> 2, j = rem & 3;
        float w = 0.f;
        if (o < 128)      w = Wqk[(l * 128 + o) * 128 + j];
        else if (o < 252) w = Wv[(l * 124 + (o - 128)) * 128 + j];
        g_wpos[i] = w;
    }
}

// ---------------- K1: kNN v3 (warp-per-point, lane-distributed sorted top-16) ----------------
__global__ __launch_bounds__(256) void knn_kernel(const float* __restrict__ x) {
    int blk = blockIdx.x;            // 0..4095
    int bt = blk >> 6, seg = blk & 63;
    int b = bt / Tt, t = bt % Tt;
    int tid = threadIdx.x, wid = tid >> 5, lane = tid & 31;
    int n = seg * 8 + wid;

    __shared__ __align__(16) float4 pool[1536];   // 24 KB
    const float* xb = x + (size_t)b * Cc * TNc;
    for (int idx = tid; idx < 1536; idx += 256) {
        int s = idx >> 9, j = idx & 511;
        int tp = t - 1 + s; tp = tp < 0 ? 0 : (tp > Tt - 1 ? Tt - 1 : tp);
        float cx = xb[0 * TNc + tp * Nn + j];
        float cy = xb[1 * TNc + tp * Nn + j];
        float cz = xb[2 * TNc + tp * Nn + j];
        float cc = fmaf(cx, cx, fmaf(cy, cy, cz * cz));
        pool[idx] = make_float4(cx, cy, cz, cc);
    }
    __syncthreads();

    float px = xb[0 * TNc + t * Nn + n];
    float py = xb[1 * TNc + t * Nn + n];
    float pz = xb[2 * TNc + t * Nn + n];

    unsigned long long S = ~0ull;
    unsigned long long thresh = ~0ull;   // 16th best (lane 15's S)

    for (int c0 = 0; c0 < 1536; c0 += 32) {
        int j = c0 + lane;
        float4 cd = pool[j];
        float e = fmaf(-2.f, fmaf(px, cd.x, fmaf(py, cd.y, pz * cd.z)), cd.w);
        unsigned bits = __float_as_uint(e);
        unsigned u = bits ^ ((unsigned)((int)bits >> 31) | 0x80000000u);
        unsigned long long kk = ((unsigned long long)u << 32) | (unsigned)j;

        unsigned mask = __ballot_sync(0xFFFFFFFFu, kk < thresh);
        while (mask) {
            int src = __ffs(mask) - 1;          // ascending j => exact tie order
            mask &= mask - 1;
            unsigned long long val = __shfl_sync(0xFFFFFFFFu, kk, src);
            if (val < thresh) {
                unsigned long long up = __shfl_up_sync(0xFFFFFFFFu, S, 1);
                if (lane < 16 && val < S)
                    S = (lane > 0 && val < up) ? up : val;
                thresh = __shfl_sync(0xFFFFFFFFu, S, 15);
            }
        }
    }

    if (lane < 16) {
        unsigned pj = (unsigned)(S & 0xFFFFFFFFu);
        int s = (int)(pj >> 9), jn = (int)(pj & 511u);
        int tp = t - 1 + s; tp = tp < 0 ? 0 : (tp > Tt - 1 ? Tt - 1 : tp);
        g_nid[(bt * Nn + n) * Kn + lane] = (b * Tt + tp) * Nn + jn;
    }
}

// ---------------- K2: projection GEMM (1008x62) @ (62 x 32768) ----------------
__global__ __launch_bounds__(256) void proj_kernel(const float* __restrict__ x) {
    __shared__ __align__(16) float Xs[62][128];
    int p0 = blockIdx.x * 128;
    int b = p0 / TNc, rem0 = p0 % TNc;
    const float* xb = x + ((size_t)b * Cc + 4) * TNc + rem0;
    for (int idx = threadIdx.x; idx < 62 * 128; idx += 256) {
        int c = idx >> 7, pp = idx & 127;
        Xs[c][pp] = xb[(size_t)c * TNc + pp];
    }
    __syncthreads();

    int tx = threadIdx.x & 31, ty = threadIdx.x >> 5;
    float* outBase = g_proj + (size_t)(p0 + tx * 4) * 1024;

    for (int chunk = 0; chunk < 16; chunk++) {
        int r0 = ty * 128 + chunk * 8;
        float acc[8][4];
#pragma unroll
        for (int rr = 0; rr < 8; rr++) {
            float bb = g_bias[r0 + rr];
#pragma unroll
            for (int pp = 0; pp < 4; pp++) acc[rr][pp] = bb;
        }
#pragma unroll 2
        for (int c = 0; c < 62; c++) {
            const float4 xv = *(const float4*)&Xs[c][tx * 4];
            const float4 wa = *(const float4*)&g_wcombT[c * 1024 + r0];
            const float4 wb = *(const float4*)&g_wcombT[c * 1024 + r0 + 4];
            float wv[8] = {wa.x, wa.y, wa.z, wa.w, wb.x, wb.y, wb.z, wb.w};
            float xvv[4] = {xv.x, xv.y, xv.z, xv.w};
#pragma unroll
            for (int rr = 0; rr < 8; rr++)
#pragma unroll
                for (int pp = 0; pp < 4; pp++)
                    acc[rr][pp] = fmaf(wv[rr], xvv[pp], acc[rr][pp]);
        }
#pragma unroll
        for (int pp = 0; pp < 4; pp++) {
            float* dst = outBase + (size_t)pp * 1024 + r0;
            *(float4*)dst       = make_float4(acc[0][pp], acc[1][pp], acc[2][pp], acc[3][pp]);
            *(float4*)(dst + 4) = make_float4(acc[4][pp], acc[5][pp], acc[6][pp], acc[7][pp]);
        }
    }
}

// ---------------- K3: attention v5 ----------------
// Per group: qk[16][132]=2112 | eS[16][17]=272 | delta8[8][16]f4=512 | nid8[8][16]=128 -> 3024, pad 3040
#define GSTR 3040
#define SM_FLOATS (2 * GSTR + 2048 + 2048)

__device__ __forceinline__ void bar_group(int gi) {
    asm volatile("bar.sync %0, 128;" :: "r"(gi + 1) : "memory");
}

__global__ __launch_bounds__(256, 4) void attn_kernel(const float* __restrict__ x,
                                                      float* __restrict__ out) {
    __shared__ __align__(16) float sm[SM_FLOATS];
    int tid = threadIdx.x;
    int gi = tid >> 7, gt = tid & 127;
    int lane = gt & 31;

    float*  qk      = sm + gi * GSTR;                  // [16][132]
    float*  eS      = sm + gi * GSTR + 2112;           // [16][17]
    float4* delta8  = (float4*)(sm + gi * GSTR + 2384); // [8 pts][16]
    int*    nid8    = (int*)(sm + gi * GSTR + 2896);    // [8 pts][16]
    float*  wposS   = sm + 2 * GSTR;
    float*  outS    = sm + 2 * GSTR + 2048;            // [16][128] (one layer)

    int p0 = blockIdx.x * 16;
    int b = p0 / TNc, rem0 = p0 % TNc;

    for (int i = tid; i < 2048; i += 256) wposS[i] = g_wpos[i];
    // ph0 for ALL 8 points of this group, once (layer-independent):
    // 128 threads = 8 points x 16 neighbors
    {
        int it = gt >> 4, i = gt & 15;
        int pt = gi * 8 + it;
        int p = p0 + pt;
        int gg = g_nid[p * Kn + i];
        nid8[it * 16 + i] = gg;
        int grem = gg - b * TNc;
        float4 d;
        d.x = x[((size_t)b * Cc + 0) * TNc + rem0 + pt] - x[((size_t)b * Cc + 0) * TNc + grem];
        d.y = x[((size_t)b * Cc + 1) * TNc + rem0 + pt] - x[((size_t)b * Cc + 1) * TNc + grem];
        d.z = x[((size_t)b * Cc + 2) * TNc + rem0 + pt] - x[((size_t)b * Cc + 2) * TNc + grem];
        d.w = x[((size_t)b * Cc + 3) * TNc + rem0 + pt] - x[((size_t)b * Cc + 3) * TNc + grem];
        delta8[it * 16 + i] = d;
    }
    if (tid < 64) {
        int pt = tid >> 2, cc = tid & 3;
        outS[pt * 128 + cc] = x[((size_t)b * Cc + cc) * TNc + rem0 + pt];
    }
    __syncthreads();

    int cch = gt < 124 ? gt : 0;   // clamped v-channel for tail lanes

    for (int l = 0; l < Ll; l++) {
        for (int it = 0; it < 8; it++) {
            int pt = gi * 8 + it;
            int p = p0 + pt;
            const float*  rowC   = g_proj + (size_t)p * 1024 + l * 512;
            const int*    nidS   = nid8 + it * 16;
            const float4* deltaS = delta8 + it * 16;

            // ph1: assemble q,k (i-major). thread = channel c = gt
            {
                float4 w4 = *(const float4*)&wposS[l * 1024 + gt * 4];
                float base = rowC[gt];
#pragma unroll
                for (int i = 0; i < 16; i++) {
                    float4 dd = deltaS[i];
                    float nbv = __ldg(&g_proj[(size_t)nidS[i] * 1024 + l * 512 + 256 + gt]);
                    qk[i * 132 + gt] = nbv + base + w4.x * dd.x + w4.y * dd.y
                                       + w4.z * dd.z + w4.w * dd.w;
                }
            }
            bar_group(gi);

            // ph2: prefetch v-gather into regs, then energy
            float vreg[16];
            {
#pragma unroll
                for (int i = 0; i < 16; i++)
                    vreg[i] = __ldg(&g_proj[(size_t)nidS[i] * 1024 + l * 512 + 384 + cch]);

                int i = gt >> 3, jh = gt & 7;
                const float* qb = qk + i * 132;
                const float* k0 = qk + jh * 132 + 64;
                const float* k1 = qk + (jh + 8) * 132 + 64;
                float a0 = 0.f, a1 = 0.f;
#pragma unroll
                for (int c4 = 0; c4 < 16; c4++) {
                    float4 q4 = *(const float4*)(qb + c4 * 4);
                    float4 ka = *(const float4*)(k0 + c4 * 4);
                    float4 kb = *(const float4*)(k1 + c4 * 4);
                    a0 = fmaf(q4.x, ka.x, a0); a0 = fmaf(q4.y, ka.y, a0);
                    a0 = fmaf(q4.z, ka.z, a0); a0 = fmaf(q4.w, ka.w, a0);
                    a1 = fmaf(q4.x, kb.x, a1); a1 = fmaf(q4.y, kb.y, a1);
                    a1 = fmaf(q4.z, kb.z, a1); a1 = fmaf(q4.w, kb.w, a1);
                }
                eS[i * 17 + jh] = a0 * 0.125f;
                eS[i * 17 + jh + 8] = a1 * 0.125f;
            }
            bar_group(gi);

            // ph3+4: in-warp redundant softmax + out (no intervening barrier)
            {
                float af = 0.f;
                float4 dd = make_float4(0.f, 0.f, 0.f, 0.f);
                if (lane < 16) {
                    const float* er = eS + lane * 17;
                    float m = -1e30f;
#pragma unroll
                    for (int j = 0; j < 16; j++) m = fmaxf(m, er[j]);
                    float sum = 0.f;
#pragma unroll
                    for (int j = 0; j < 16; j++) sum += __expf(er[j] - m);
                    af = __expf(er[0] - m) / sum;
                    dd = deltaS[lane];
                }
                float s0 = af, dx = af * dd.x, dy = af * dd.y, dz = af * dd.z, dw = af * dd.w;
#pragma unroll
                for (int off = 16; off > 0; off >>= 1) {
                    s0 += __shfl_xor_sync(0xFFFFFFFFu, s0, off);
                    dx += __shfl_xor_sync(0xFFFFFFFFu, dx, off);
                    dy += __shfl_xor_sync(0xFFFFFFFFu, dy, off);
                    dz += __shfl_xor_sync(0xFFFFFFFFu, dz, off);
                    dw += __shfl_xor_sync(0xFFFFFFFFu, dw, off);
                }
                float4 wv = *(const float4*)&wposS[l * 1024 + (128 + cch) * 4];
                float acc = s0 * rowC[128 + cch]
                          + wv.x * dx + wv.y * dy + wv.z * dz + wv.w * dw;
#pragma unroll
                for (int i = 0; i < 16; i++) {
                    float afi = __shfl_sync(0xFFFFFFFFu, af, i);
                    acc = fmaf(afi, vreg[i], acc);
                }
                if (gt < 124) outS[pt * 128 + 4 + gt] = acc;
            }
            bar_group(gi);   // WAR guard on qk/eS before next assemble
        }
        // flush this layer's 16 points (whole block)
        __syncthreads();
        for (int idx = tid; idx < 2048; idx += 256) {
            int c = idx >> 4, pt = idx & 15;
            out[((size_t)(l * Bb + b) * 128 + c) * TNc + rem0 + pt] = outS[pt * 128 + c];
        }
        __syncthreads();
    }
}

// ---------------- launch ----------------
extern "C" void kernel_launch(void* const* d_in, const int* in_sizes, int n_in,
                              void* d_out, int out_size) {
    const float* x   = (const float*)d_in[0];
    const float* Wqk = (const float*)d_in[1];
    const float* bqk = (const float*)d_in[2];
    const float* Wv  = (const float*)d_in[3];
    const float* bv  = (const float*)d_in[4];
    float* out = (float*)d_out;

    prep_kernel<<<256, 256>>>(Wqk, bqk, Wv, bv);
    knn_kernel<<<4096, 256>>>(x);
    proj_kernel<<<BTNc / 128, 256>>>(x);
    attn_kernel<<<BTNc / 16, 256>>>(x, out);
}